// round 7
// baseline (speedup 1.0000x reference)
#include <cuda_runtime.h>
#include <math.h>
#include <stdint.h>

#define NN 200000
#define FF 128
#define EE 600000
#define KP 20        // staged-chunk k-stride (conflict-free fragment loads)
#define HS 260       // resident h row stride (260 mod 32 == 4 -> conflict-free)
#define CS 132       // Cst row stride

// ---------------- scratch ----------------
__device__ int g_min1[NN];
__device__ int g_min2[NN];
__device__ __align__(16) float g_w1t[256 * 384];  // tf32-rounded, w1t[n][k]
__device__ __align__(16) float g_w2t[128 * 256];  // tf32-rounded, w2t[n][k]

// ---------------- helpers ----------------
__device__ __forceinline__ uint32_t tf32r(float f) {
    uint32_t u;
    asm("cvt.rna.tf32.f32 %0, %1;" : "=r"(u) : "f"(f));
    return u;
}
__device__ __forceinline__ void mma8(float* c, const uint32_t* a, const uint32_t* b) {
    asm volatile(
        "mma.sync.aligned.m16n8k8.row.col.f32.tf32.tf32.f32 "
        "{%0,%1,%2,%3}, {%4,%5,%6,%7}, {%8,%9}, {%0,%1,%2,%3};"
        : "+f"(c[0]), "+f"(c[1]), "+f"(c[2]), "+f"(c[3])
        : "r"(a[0]), "r"(a[1]), "r"(a[2]), "r"(a[3]), "r"(b[0]), "r"(b[1]));
}
__device__ __forceinline__ uint32_t sptr(const void* p) {
    uint32_t a;
    asm("{ .reg .u64 t; cvta.to.shared.u64 t, %1; cvt.u32.u64 %0, t; }" : "=r"(a) : "l"(p));
    return a;
}
__device__ __forceinline__ void cp16(uint32_t dst, const void* src) {
    asm volatile("cp.async.ca.shared.global [%0], [%1], 16;" :: "r"(dst), "l"(src) : "memory");
}
#define CP_COMMIT() asm volatile("cp.async.commit_group;" ::: "memory")
#define CP_WAIT0()  asm volatile("cp.async.wait_group 0;" ::: "memory")

// ---------------- graph kernels ----------------
__global__ void k_init() {
    int i = blockIdx.x * blockDim.x + threadIdx.x;
    if (i < NN) { g_min1[i] = NN; g_min2[i] = NN; }
}
__global__ void k_pass1(const int* __restrict__ ei) {
    int e = blockIdx.x * blockDim.x + threadIdx.x;
    if (e >= EE) return;
    int s = ei[e], d = ei[EE + e];
    if (s != d) { atomicMin(&g_min1[s], d); atomicMin(&g_min1[d], s); }
}
__global__ void k_pass2(const int* __restrict__ ei) {
    int e = blockIdx.x * blockDim.x + threadIdx.x;
    if (e >= EE) return;
    int s = ei[e], d = ei[EE + e];
    if (s != d) {
        if (d != g_min1[s]) atomicMin(&g_min2[s], d);
        if (s != g_min1[d]) atomicMin(&g_min2[d], s);
    }
}
__global__ void k_prep(const float* __restrict__ w1, const float* __restrict__ w2) {
    int i = blockIdx.x * blockDim.x + threadIdx.x;
    if (i < 256 * 384) {
        int n = i / 384, k = i % 384;
        g_w1t[i] = __uint_as_float(tf32r(w1[k * 256 + n]));
    }
    if (i < 128 * 256) {
        int n = i / 256, k = i % 256;
        g_w2t[i] = __uint_as_float(tf32r(w2[k * 128 + n]));
    }
}

// ---------------------------------------------------------------------------
// Fused: GEMM1(128x256,K=384) -> h in SMEM -> GEMM2(128x128,K=256)
//        -> bias+LN -> output select -> murray head.  256 thr, occ 1.
// Warps: 2(m) x 4(n).  GEMM1 warp tile 64x64; GEMM2 warp tile 64x32.
// ---------------------------------------------------------------------------
// dynamic smem words:
//   region1 [0 .. 33280): As1[2][2560] / Bs1@5120[2][5120]  (aliased with)
//                         sH[128*260]  (aliased with) Cst[128*132]
//   Bs2 @ 33280: [2][2560]
//   mw1s @ 38400: [8192]
#define DSM_WORDS (33280 + 5120 + 8192)
#define DSM_BYTES (DSM_WORDS * 4)

__global__ void __launch_bounds__(256, 1) k_fused(
    const float* __restrict__ x,
    const float* __restrict__ b1, const float* __restrict__ b2,
    const float* __restrict__ lng, const float* __restrict__ lnb,
    const int* __restrict__ types,
    const float* __restrict__ mw1, const float* __restrict__ mb1,
    const float* __restrict__ mw2, const float* __restrict__ mb2,
    float* __restrict__ out)
{
    extern __shared__ uint32_t dsm[];
    uint32_t* As1 = dsm;            // [2][2560]
    uint32_t* Bs1 = dsm + 5120;     // [2][5120]
    uint32_t* sH  = dsm;            // [128*HS]
    float*    Cst = (float*)dsm;    // [128*CS]
    uint32_t* Bs2 = dsm + 33280;    // [2][2560]
    float*    mw1s = (float*)(dsm + 38400);

    __shared__ int   sN0[128], sN1[128], sCls[128];
    __shared__ float sb1[256], sb2v[128], slg[128], slb[128], smb1[64], smw2[64];

    const int t = threadIdx.x, lane = t & 31, w = t >> 5;
    const int r0 = blockIdx.x * 128;
    const int mw = w >> 2, nw = w & 3;          // 2m x 4n
    const int gid = lane >> 2, tig = lane & 3;
    const int row = t >> 1, kh = (t & 1) * 8;   // staging map
    const int selfr = min(r0 + row, NN - 1);

    // ---- init shared state ----
    if (t < 128) {
        int r = min(r0 + t, NN - 1);
        int m1 = g_min1[r], m2 = g_min2[r];
        sN0[t] = min(m1, NN - 1);
        sN1[t] = min(m2, NN - 1);
        sCls[t] = (types[r] == 1) ? ((m1 < NN && m2 < NN) ? 2 : 1) : 0;
        sb2v[t] = b2[t]; slg[t] = lng[t]; slb[t] = lnb[t];
    }
    sb1[t] = b1[t];
    if (t < 64) { smb1[t] = mb1[t]; smw2[t] = mw2[t]; }
    for (int i = t; i < 8192; i += 256) mw1s[i] = mw1[i];

    const uint32_t bs1b = sptr(Bs1);
    const uint32_t bs2b = sptr(Bs2);

    // =================== GEMM1: acc = ctx @ w1t^T ======================
    float acc[4][8][4];
#pragma unroll
    for (int ms = 0; ms < 4; ms++)
#pragma unroll
        for (int nt = 0; nt < 8; nt++)
#pragma unroll
            for (int j = 0; j < 4; j++) acc[ms][nt][j] = 0.f;

    // prologue: B(0) via cp.async, A(0) via LDG
    {
        const float* gsrc = g_w1t + (size_t)t * 384;
#pragma unroll
        for (int j = 0; j < 4; j++)
            cp16(bs1b + (t * 20 + j * 4) * 4, gsrc + j * 4);
        CP_COMMIT();
        const float4* ap = (const float4*)(x + (size_t)selfr * 128 + kh);
        float4 av0 = ap[0], av1 = ap[1];
        CP_WAIT0();
        uint4 u0 = { tf32r(av0.x), tf32r(av0.y), tf32r(av0.z), tf32r(av0.w) };
        uint4 u1 = { tf32r(av1.x), tf32r(av1.y), tf32r(av1.z), tf32r(av1.w) };
        *(uint4*)&As1[row * 20 + kh]     = u0;
        *(uint4*)&As1[row * 20 + kh + 4] = u1;
    }
    __syncthreads();

    for (int c = 0; c < 24; c++) {
        const int cur = c & 1, nxt = cur ^ 1;
        float4 av0, av1;
        if (c < 23) {
            const int cn = c + 1;
            const float* gsrc = g_w1t + (size_t)t * 384 + cn * 16;
#pragma unroll
            for (int j = 0; j < 4; j++)
                cp16(bs1b + (nxt * 5120 + t * 20 + j * 4) * 4, gsrc + j * 4);
            CP_COMMIT();
            const int sel = cn >> 3;
            const int src = (sel == 0) ? selfr : (sel == 1 ? sN0[row] : sN1[row]);
            const float4* ap = (const float4*)(x + (size_t)src * 128 + (cn & 7) * 16 + kh);
            av0 = ap[0]; av1 = ap[1];
        }
        // compute chunk c
        const uint32_t* A = As1 + cur * 2560;
        const uint32_t* B = Bs1 + cur * 5120;
#pragma unroll
        for (int k8 = 0; k8 < 2; k8++) {
            const int kb = k8 * 8;
            uint32_t af[4][4];
#pragma unroll
            for (int ms = 0; ms < 4; ms++) {
                int m = mw * 64 + ms * 16 + gid;
                af[ms][0] = A[m * 20 + kb + tig];
                af[ms][1] = A[(m + 8) * 20 + kb + tig];
                af[ms][2] = A[m * 20 + kb + tig + 4];
                af[ms][3] = A[(m + 8) * 20 + kb + tig + 4];
            }
#pragma unroll
            for (int nt = 0; nt < 8; nt++) {
                int n = nw * 64 + nt * 8 + gid;
                uint32_t bf[2] = { B[n * 20 + kb + tig], B[n * 20 + kb + tig + 4] };
#pragma unroll
                for (int ms = 0; ms < 4; ms++) mma8(acc[ms][nt], af[ms], bf);
            }
        }
        if (c < 23) {
            CP_WAIT0();
            uint4 u0 = { tf32r(av0.x), tf32r(av0.y), tf32r(av0.z), tf32r(av0.w) };
            uint4 u1 = { tf32r(av1.x), tf32r(av1.y), tf32r(av1.z), tf32r(av1.w) };
            *(uint4*)&As1[nxt * 2560 + row * 20 + kh]     = u0;
            *(uint4*)&As1[nxt * 2560 + row * 20 + kh + 4] = u1;
            __syncthreads();
        }
    }
    __syncthreads();   // all GEMM1 reads done before h overwrites region1

    // ---- epilogue1: bias + relu -> resident h (tf32 bits) ----
#pragma unroll
    for (int ms = 0; ms < 4; ms++) {
        int r1 = mw * 64 + ms * 16 + gid;
#pragma unroll
        for (int nt = 0; nt < 8; nt++) {
            int col = nw * 64 + nt * 8 + tig * 2;
            float bb0 = sb1[col], bb1 = sb1[col + 1];
            uint2 lo = { tf32r(fmaxf(acc[ms][nt][0] + bb0, 0.f)),
                         tf32r(fmaxf(acc[ms][nt][1] + bb1, 0.f)) };
            uint2 hi = { tf32r(fmaxf(acc[ms][nt][2] + bb0, 0.f)),
                         tf32r(fmaxf(acc[ms][nt][3] + bb1, 0.f)) };
            *(uint2*)&sH[r1 * HS + col]       = lo;
            *(uint2*)&sH[(r1 + 8) * HS + col] = hi;
        }
    }

    // =================== GEMM2: acc2 = h @ w2t^T =======================
    float acc2[4][4][4];
#pragma unroll
    for (int ms = 0; ms < 4; ms++)
#pragma unroll
        for (int nt = 0; nt < 4; nt++)
#pragma unroll
            for (int j = 0; j < 4; j++) acc2[ms][nt][j] = 0.f;

    {   // prologue B2(0)
        const float* gsrc = g_w2t + (size_t)row * 256 + kh;
        cp16(bs2b + (row * 20 + kh) * 4, gsrc);
        cp16(bs2b + (row * 20 + kh + 4) * 4, gsrc + 4);
        CP_COMMIT(); CP_WAIT0();
    }
    __syncthreads();   // h visible + B2(0) visible

    for (int c = 0; c < 16; c++) {
        const int cur = c & 1, nxt = cur ^ 1;
        if (c < 15) {
            const float* gsrc = g_w2t + (size_t)row * 256 + (c + 1) * 16 + kh;
            cp16(bs2b + (nxt * 2560 + row * 20 + kh) * 4, gsrc);
            cp16(bs2b + (nxt * 2560 + row * 20 + kh + 4) * 4, gsrc + 4);
            CP_COMMIT();
        }
        const uint32_t* B = Bs2 + cur * 2560;
#pragma unroll
        for (int k8 = 0; k8 < 2; k8++) {
            const int k0 = c * 16 + k8 * 8;
            uint32_t af[4][4];
#pragma unroll
            for (int ms = 0; ms < 4; ms++) {
                int m = mw * 64 + ms * 16 + gid;
                af[ms][0] = sH[m * HS + k0 + tig];
                af[ms][1] = sH[(m + 8) * HS + k0 + tig];
                af[ms][2] = sH[m * HS + k0 + tig + 4];
                af[ms][3] = sH[(m + 8) * HS + k0 + tig + 4];
            }
#pragma unroll
            for (int nt = 0; nt < 4; nt++) {
                int n = nw * 32 + nt * 8 + gid;
                uint32_t bf[2] = { B[n * 20 + k8 * 8 + tig], B[n * 20 + k8 * 8 + tig + 4] };
#pragma unroll
                for (int ms = 0; ms < 4; ms++) mma8(acc2[ms][nt], af[ms], bf);
            }
        }
        if (c < 15) { CP_WAIT0(); __syncthreads(); }
    }
    __syncthreads();   // all sH reads done before Cst overwrites region1

    // ---- epilogue2: bias -> Cst ----
#pragma unroll
    for (int ms = 0; ms < 4; ms++) {
        int r1 = mw * 64 + ms * 16 + gid;
#pragma unroll
        for (int nt = 0; nt < 4; nt++) {
            int col = nw * 32 + nt * 8 + tig * 2;
            Cst[r1 * CS + col]           = acc2[ms][nt][0] + sb2v[col];
            Cst[r1 * CS + col + 1]       = acc2[ms][nt][1] + sb2v[col + 1];
            Cst[(r1 + 8) * CS + col]     = acc2[ms][nt][2] + sb2v[col];
            Cst[(r1 + 8) * CS + col + 1] = acc2[ms][nt][3] + sb2v[col + 1];
        }
    }
    __syncthreads();

    // ---- LayerNorm per row ----
    if (t < 128) {
        float* rp = Cst + t * CS;
        float s = 0.f, q = 0.f;
#pragma unroll
        for (int j = 0; j < 32; j++) {
            float4 v = ((const float4*)rp)[j];
            s += v.x + v.y + v.z + v.w;
            q += v.x * v.x + v.y * v.y + v.z * v.z + v.w * v.w;
        }
        float mean = s * (1.f / 128.f);
        float var  = q * (1.f / 128.f) - mean * mean;
        float rs   = rsqrtf(var + 1e-5f);
#pragma unroll
        for (int j = 0; j < 32; j++) {
            float4 v = ((const float4*)rp)[j];
            v.x = (v.x - mean) * rs * slg[4 * j]     + slb[4 * j];
            v.y = (v.y - mean) * rs * slg[4 * j + 1] + slb[4 * j + 1];
            v.z = (v.z - mean) * rs * slg[4 * j + 2] + slb[4 * j + 2];
            v.w = (v.w - mean) * rs * slg[4 * j + 3] + slb[4 * j + 3];
            ((float4*)rp)[j] = v;
        }
    }
    __syncthreads();

    // ---- coalesced output: upd ? proc : x ----
    {
        const float4* x4 = (const float4*)x;
        float4* o4 = (float4*)out;
        for (int idx = t; idx < 128 * 32; idx += 256) {
            int rl = idx >> 5, c4 = idx & 31;
            int rg = r0 + rl;
            if (rg < NN) {
                float4 v = (sCls[rl] == 2) ? ((const float4*)(Cst + rl * CS))[c4]
                                           : x4[(size_t)rg * 32 + c4];
                o4[(size_t)rg * 32 + c4] = v;
            }
        }
    }

    // ---- murray head (warp per row) ----
    {
        const float bias2 = mb2[0];
        float* mo = out + (size_t)NN * FF;
        for (int rl = w; rl < 128; rl += 8) {
            int rg = r0 + rl;
            if (rg >= NN) continue;
            int cls = sCls[rl];
            if (cls != 2) {
                if (lane == 0) mo[rg] = (cls == 1) ? 0.5f : 0.f;
                continue;
            }
            float4 pr = ((const float4*)(Cst + rl * CS))[lane];
            float m0 = smb1[2 * lane], m1 = smb1[2 * lane + 1];
#pragma unroll
            for (int k4 = 0; k4 < 32; k4++) {
                float vx = __shfl_sync(0xffffffffu, pr.x, k4);
                float vy = __shfl_sync(0xffffffffu, pr.y, k4);
                float vz = __shfl_sync(0xffffffffu, pr.z, k4);
                float vw = __shfl_sync(0xffffffffu, pr.w, k4);
                float2 w0  = ((const float2*)&mw1s[(k4 * 4 + 0) * 64])[lane];
                float2 w1v = ((const float2*)&mw1s[(k4 * 4 + 1) * 64])[lane];
                float2 w2v = ((const float2*)&mw1s[(k4 * 4 + 2) * 64])[lane];
                float2 w3v = ((const float2*)&mw1s[(k4 * 4 + 3) * 64])[lane];
                m0 = fmaf(vx, w0.x, fmaf(vy, w1v.x, fmaf(vz, w2v.x, fmaf(vw, w3v.x, m0))));
                m1 = fmaf(vx, w0.y, fmaf(vy, w1v.y, fmaf(vz, w2v.y, fmaf(vw, w3v.y, m1))));
            }
            float p = fmaxf(m0, 0.f) * smw2[2 * lane] + fmaxf(m1, 0.f) * smw2[2 * lane + 1];
#pragma unroll
            for (int m = 16; m; m >>= 1) p += __shfl_xor_sync(0xffffffffu, p, m);
            if (lane == 0) mo[rg] = 1.f / (1.f + expf(-(p + bias2)));
        }
    }
}

// ---------------------------------------------------------------------------
extern "C" void kernel_launch(void* const* d_in, const int* in_sizes, int n_in,
                              void* d_out, int out_size) {
    const float* x   = (const float*)d_in[0];
    const int*   ei  = (const int*)d_in[1];
    const int*   ty  = (const int*)d_in[2];
    const float* w1  = (const float*)d_in[3];
    const float* b1  = (const float*)d_in[4];
    const float* w2  = (const float*)d_in[5];
    const float* b2  = (const float*)d_in[6];
    const float* lng = (const float*)d_in[7];
    const float* lnb = (const float*)d_in[8];
    const float* mw1 = (const float*)d_in[9];
    const float* mb1 = (const float*)d_in[10];
    const float* mw2 = (const float*)d_in[11];
    const float* mb2 = (const float*)d_in[12];
    float* out = (float*)d_out;

    cudaFuncSetAttribute(k_fused, cudaFuncAttributeMaxDynamicSharedMemorySize, DSM_BYTES);

    k_init<<<(NN + 255) / 256, 256>>>();
    k_pass1<<<(EE + 255) / 256, 256>>>(ei);
    k_pass2<<<(EE + 255) / 256, 256>>>(ei);
    k_prep<<<(256 * 384 + 255) / 256, 256>>>(w1, w2);
    k_fused<<<(NN + 127) / 128, 256, DSM_BYTES>>>(x, b1, b2, lng, lnb, ty,
                                                  mw1, mb1, mw2, mb2, out);
}

// round 9
// speedup vs baseline: 1.3670x; 1.3670x over previous
#include <cuda_runtime.h>
#include <math.h>
#include <stdint.h>

#define NN 200000
#define FF 128
#define EE 600000
#define KP 20            // padded smem k-stride
#define MAXSLOT 200064   // 1563 * 128

// ---------------- scratch ----------------
__device__ int g_min1[NN];
__device__ int g_min2[NN];
__device__ int g_cnt;
__device__ int g_list[MAXSLOT];
__device__ int g_ln0[MAXSLOT];
__device__ int g_ln1[MAXSLOT];
__device__ __align__(16) float g_w1t[256 * 384];          // tf32-rounded, w1t[n][k]
__device__ __align__(16) float g_w2t[128 * 256];          // tf32-rounded, w2t[n][k]
__device__ __align__(16) float g_hc[(size_t)MAXSLOT * 256];   // compact h
__device__ __align__(16) float g_procc[(size_t)MAXSLOT * 128];// compact proc

// ---------------- helpers ----------------
__device__ __forceinline__ uint32_t tf32r(float f) {
    uint32_t u;
    asm("cvt.rna.tf32.f32 %0, %1;" : "=r"(u) : "f"(f));
    return u;
}
__device__ __forceinline__ void mma8(float* c, const uint32_t* a, const uint32_t* b) {
    asm volatile(
        "mma.sync.aligned.m16n8k8.row.col.f32.tf32.tf32.f32 "
        "{%0,%1,%2,%3}, {%4,%5,%6,%7}, {%8,%9}, {%0,%1,%2,%3};"
        : "+f"(c[0]), "+f"(c[1]), "+f"(c[2]), "+f"(c[3])
        : "r"(a[0]), "r"(a[1]), "r"(a[2]), "r"(a[3]), "r"(b[0]), "r"(b[1]));
}

// ---------------- setup: init mins + count + weight prep ----------------
// grid MUST cover NN (782 blocks), not just the weight range.
__global__ void k_init(const float* __restrict__ w1, const float* __restrict__ w2) {
    int i = blockIdx.x * blockDim.x + threadIdx.x;
    if (i == 0) g_cnt = 0;
    if (i < NN) { g_min1[i] = NN; g_min2[i] = NN; }
    if (i < 256 * 384) {
        int n = i / 384, k = i % 384;
        g_w1t[i] = __uint_as_float(tf32r(w1[k * 256 + n]));
    }
    if (i < 128 * 256) {
        int n = i / 256, k = i % 256;
        g_w2t[i] = __uint_as_float(tf32r(w2[k * 128 + n]));
    }
}
__global__ void k_pass1(const int* __restrict__ ei) {
    int e = blockIdx.x * blockDim.x + threadIdx.x;
    if (e >= EE) return;
    int s = ei[e], d = ei[EE + e];
    if (s != d) { atomicMin(&g_min1[s], d); atomicMin(&g_min1[d], s); }
}
__global__ void k_pass2(const int* __restrict__ ei) {
    int e = blockIdx.x * blockDim.x + threadIdx.x;
    if (e >= EE) return;
    int s = ei[e], d = ei[EE + e];
    if (s != d) {
        if (d != g_min1[s]) atomicMin(&g_min2[s], d);
        if (s != g_min1[d]) atomicMin(&g_min2[d], s);
    }
}

// ---------------- dense copy out = x (gemm2 overwrites updated rows) -----
__global__ void __launch_bounds__(256) k_copy(const float* __restrict__ x,
                                              float* __restrict__ out) {
    int row = blockIdx.x * 8 + (threadIdx.x >> 5);
    if (row >= NN) return;
    int c = threadIdx.x & 31;
    ((float4*)out)[(size_t)row * 32 + c] = ((const float4*)x)[(size_t)row * 32 + c];
}

// ---------------- classify + compact + murray defaults -------------------
__global__ void k_class(const int* __restrict__ types, float* __restrict__ out) {
    int r = blockIdx.x * blockDim.x + threadIdx.x;
    if (r >= NN) return;
    int m1 = g_min1[r], m2 = g_min2[r];
    int cls = (types[r] == 1) ? ((m1 < NN && m2 < NN) ? 2 : 1) : 0;
    out[(size_t)NN * FF + r] = (cls == 1) ? 0.5f : 0.f;  // cls==2 overwritten later
    if (cls == 2) {
        int slot = atomicAdd(&g_cnt, 1);
        g_list[slot] = r;
        g_ln0[slot] = m1;
        g_ln1[slot] = m2;
    }
}

// ---------------------------------------------------------------------------
// GEMM1 compact: g_hc[slot] = relu([x[self]|x[n0]|x[n1]] @ w1 + b1)
// grid (2, 1563) fixed, early exit on g_cnt. 128x128 tile, K=384/24 chunks.
// ---------------------------------------------------------------------------
__global__ void __launch_bounds__(256, 2) k_gemm1c(const float* __restrict__ x,
                                                   const float* __restrict__ b1) {
    const int r0 = blockIdx.y * 128;
    const int cnt = g_cnt;
    if (r0 >= cnt) return;

    __shared__ uint32_t As[2][128 * KP];
    __shared__ uint32_t Bs[2][128 * KP];
    __shared__ int sSelf[128], sN0[128], sN1[128];

    const int t = threadIdx.x, lane = t & 31, w = t >> 5;
    const int bx = blockIdx.x;

    if (t < 128) {
        int slot = r0 + t;
        bool ok = slot < cnt;
        sSelf[t] = ok ? g_list[slot] : 0;
        sN0[t]   = ok ? g_ln0[slot] : 0;
        sN1[t]   = ok ? g_ln1[slot] : 0;
    }
    __syncthreads();

    const int row = t >> 1, kh = (t & 1) * 8;
    const int mw = w & 3, nw = w >> 2;
    const int gid = lane >> 2, tig = lane & 3;

    float acc[2][8][4];
#pragma unroll
    for (int ms = 0; ms < 2; ms++)
#pragma unroll
        for (int nt = 0; nt < 8; nt++)
#pragma unroll
            for (int j = 0; j < 4; j++) acc[ms][nt][j] = 0.f;

    float4 av0, av1, bv0, bv1;
    {
        const float4* ap = (const float4*)(x + (size_t)sSelf[row] * 128 + kh);
        av0 = ap[0]; av1 = ap[1];
        const float4* bp = (const float4*)(g_w1t + (size_t)(bx * 128 + row) * 384 + kh);
        bv0 = bp[0]; bv1 = bp[1];
    }

    const int si = row * KP + kh;
    for (int c = 0; c < 24; c++) {
        const int b = c & 1;
        uint32_t* A = As[b];
        uint32_t* B = Bs[b];
        {
            uint32_t ta[8] = { tf32r(av0.x), tf32r(av0.y), tf32r(av0.z), tf32r(av0.w),
                               tf32r(av1.x), tf32r(av1.y), tf32r(av1.z), tf32r(av1.w) };
            uint32_t tbv[8] = { __float_as_uint(bv0.x), __float_as_uint(bv0.y),
                                __float_as_uint(bv0.z), __float_as_uint(bv0.w),
                                __float_as_uint(bv1.x), __float_as_uint(bv1.y),
                                __float_as_uint(bv1.z), __float_as_uint(bv1.w) };
            *(float4*)&A[si]     = *(float4*)&ta[0];
            *(float4*)&A[si + 4] = *(float4*)&ta[4];
            *(float4*)&B[si]     = *(float4*)&tbv[0];
            *(float4*)&B[si + 4] = *(float4*)&tbv[4];
        }
        __syncthreads();
        if (c + 1 < 24) {
            int cn = c + 1;
            int sel = cn >> 3, koff = (cn & 7) * 16 + kh;
            int src = (sel == 0) ? sSelf[row] : (sel == 1 ? sN0[row] : sN1[row]);
            const float4* ap = (const float4*)(x + (size_t)src * 128 + koff);
            av0 = ap[0]; av1 = ap[1];
            const float4* bp = (const float4*)(g_w1t + (size_t)(bx * 128 + row) * 384 + cn * 16 + kh);
            bv0 = bp[0]; bv1 = bp[1];
        }
#pragma unroll
        for (int k8 = 0; k8 < 2; k8++) {
            const int kb = k8 * 8;
            uint32_t af[2][4];
#pragma unroll
            for (int ms = 0; ms < 2; ms++) {
                int m = mw * 32 + ms * 16;
                af[ms][0] = A[(m + gid) * KP + kb + tig];
                af[ms][1] = A[(m + 8 + gid) * KP + kb + tig];
                af[ms][2] = A[(m + gid) * KP + kb + tig + 4];
                af[ms][3] = A[(m + 8 + gid) * KP + kb + tig + 4];
            }
#pragma unroll
            for (int nt = 0; nt < 8; nt++) {
                int n = nw * 64 + nt * 8 + gid;
                uint32_t bf[2] = { B[n * KP + kb + tig], B[n * KP + kb + tig + 4] };
                mma8(acc[0][nt], af[0], bf);
                mma8(acc[1][nt], af[1], bf);
            }
        }
        __syncthreads();
    }

    // epilogue: bias + relu -> compact h (tf32-rounded so GEMM2 skips cvt)
#pragma unroll
    for (int ms = 0; ms < 2; ms++) {
        int sl = r0 + mw * 32 + ms * 16 + gid;
#pragma unroll
        for (int nt = 0; nt < 8; nt++) {
            int col = bx * 128 + nw * 64 + nt * 8 + tig * 2;
            float bb0 = __ldg(&b1[col]), bb1 = __ldg(&b1[col + 1]);
            if (sl < cnt) {
                uint2 v = { tf32r(fmaxf(acc[ms][nt][0] + bb0, 0.f)),
                            tf32r(fmaxf(acc[ms][nt][1] + bb1, 0.f)) };
                *(uint2*)&g_hc[(size_t)sl * 256 + col] = v;
            }
            if (sl + 8 < cnt) {
                uint2 v = { tf32r(fmaxf(acc[ms][nt][2] + bb0, 0.f)),
                            tf32r(fmaxf(acc[ms][nt][3] + bb1, 0.f)) };
                *(uint2*)&g_hc[(size_t)(sl + 8) * 256 + col] = v;
            }
        }
    }
}

// ---------------------------------------------------------------------------
// GEMM2 compact + bias + LayerNorm + scatter out + stash proc
// ---------------------------------------------------------------------------
__global__ void __launch_bounds__(256, 2) k_gemm2c(const float* __restrict__ b2,
                                                   const float* __restrict__ lng,
                                                   const float* __restrict__ lnb,
                                                   float* __restrict__ out) {
    const int r0 = blockIdx.x * 128;
    const int cnt = g_cnt;
    if (r0 >= cnt) return;

    extern __shared__ char dsm[];
    uint32_t* AsB = (uint32_t*)dsm;                 // [2][128*KP]
    uint32_t* BsB = AsB + 2 * 128 * KP;             // [2][128*KP]
    float* Cst = (float*)dsm;                       // [128*132] after mainloop

    __shared__ int   sRow[128];
    __shared__ float sb2[128], slg[128], slb[128];

    const int t = threadIdx.x, lane = t & 31, w = t >> 5;

    if (t < 128) {
        int slot = r0 + t;
        sRow[t] = (slot < cnt) ? g_list[slot] : -1;
        sb2[t] = b2[t]; slg[t] = lng[t]; slb[t] = lnb[t];
    }
    __syncthreads();

    const int row = t >> 1, kh = (t & 1) * 8;
    const int aslot = min(r0 + row, cnt - 1);
    const int mw = w & 3, nw = w >> 2;
    const int gid = lane >> 2, tig = lane & 3;

    float acc[2][8][4];
#pragma unroll
    for (int ms = 0; ms < 2; ms++)
#pragma unroll
        for (int nt = 0; nt < 8; nt++)
#pragma unroll
            for (int j = 0; j < 4; j++) acc[ms][nt][j] = 0.f;

    float4 av0, av1, bv0, bv1;
    {
        const float4* ap = (const float4*)(g_hc + (size_t)aslot * 256 + kh);
        av0 = ap[0]; av1 = ap[1];
        const float4* bp = (const float4*)(g_w2t + (size_t)row * 256 + kh);
        bv0 = bp[0]; bv1 = bp[1];
    }

    const int si = row * KP + kh;
    for (int c = 0; c < 16; c++) {
        const int b = c & 1;
        uint32_t* A = AsB + b * 128 * KP;
        uint32_t* B = BsB + b * 128 * KP;
        {
            uint4 ua = { __float_as_uint(av0.x), __float_as_uint(av0.y),
                         __float_as_uint(av0.z), __float_as_uint(av0.w) };
            uint4 ub = { __float_as_uint(av1.x), __float_as_uint(av1.y),
                         __float_as_uint(av1.z), __float_as_uint(av1.w) };
            uint4 wa = { __float_as_uint(bv0.x), __float_as_uint(bv0.y),
                         __float_as_uint(bv0.z), __float_as_uint(bv0.w) };
            uint4 wb = { __float_as_uint(bv1.x), __float_as_uint(bv1.y),
                         __float_as_uint(bv1.z), __float_as_uint(bv1.w) };
            *(uint4*)&A[si]     = ua;
            *(uint4*)&A[si + 4] = ub;
            *(uint4*)&B[si]     = wa;
            *(uint4*)&B[si + 4] = wb;
        }
        __syncthreads();
        if (c + 1 < 16) {
            int cn = c + 1;
            const float4* ap = (const float4*)(g_hc + (size_t)aslot * 256 + cn * 16 + kh);
            av0 = ap[0]; av1 = ap[1];
            const float4* bp = (const float4*)(g_w2t + (size_t)row * 256 + cn * 16 + kh);
            bv0 = bp[0]; bv1 = bp[1];
        }
#pragma unroll
        for (int k8 = 0; k8 < 2; k8++) {
            const int kb = k8 * 8;
            uint32_t af[2][4];
#pragma unroll
            for (int ms = 0; ms < 2; ms++) {
                int m = mw * 32 + ms * 16;
                af[ms][0] = A[(m + gid) * KP + kb + tig];
                af[ms][1] = A[(m + 8 + gid) * KP + kb + tig];
                af[ms][2] = A[(m + gid) * KP + kb + tig + 4];
                af[ms][3] = A[(m + 8 + gid) * KP + kb + tig + 4];
            }
#pragma unroll
            for (int nt = 0; nt < 8; nt++) {
                int n = nw * 64 + nt * 8 + gid;
                uint32_t bf[2] = { B[n * KP + kb + tig], B[n * KP + kb + tig + 4] };
                mma8(acc[0][nt], af[0], bf);
                mma8(acc[1][nt], af[1], bf);
            }
        }
        __syncthreads();
    }

    // stage bias-added C
#pragma unroll
    for (int ms = 0; ms < 2; ms++) {
        int rl = mw * 32 + ms * 16 + gid;
#pragma unroll
        for (int nt = 0; nt < 8; nt++) {
            int col = nw * 64 + nt * 8 + tig * 2;
            Cst[rl * 132 + col]           = acc[ms][nt][0] + sb2[col];
            Cst[rl * 132 + col + 1]       = acc[ms][nt][1] + sb2[col + 1];
            Cst[(rl + 8) * 132 + col]     = acc[ms][nt][2] + sb2[col];
            Cst[(rl + 8) * 132 + col + 1] = acc[ms][nt][3] + sb2[col + 1];
        }
    }
    __syncthreads();

    // per-row LayerNorm
    if (t < 128) {
        float* rp = Cst + t * 132;
        float s = 0.f, q = 0.f;
#pragma unroll
        for (int j = 0; j < 32; j++) {
            float4 v = ((const float4*)rp)[j];
            s += v.x + v.y + v.z + v.w;
            q += v.x * v.x + v.y * v.y + v.z * v.z + v.w * v.w;
        }
        float mean = s * (1.f / 128.f);
        float var  = q * (1.f / 128.f) - mean * mean;
        float rs   = rsqrtf(var + 1e-5f);
#pragma unroll
        for (int j = 0; j < 32; j++) {
            float4 v = ((const float4*)rp)[j];
            v.x = (v.x - mean) * rs * slg[4 * j]     + slb[4 * j];
            v.y = (v.y - mean) * rs * slg[4 * j + 1] + slb[4 * j + 1];
            v.z = (v.z - mean) * rs * slg[4 * j + 2] + slb[4 * j + 2];
            v.w = (v.w - mean) * rs * slg[4 * j + 3] + slb[4 * j + 3];
            ((float4*)rp)[j] = v;
        }
    }
    __syncthreads();

    // scatter: out[node] = proc ; g_procc[slot] = proc
    {
        float4* o4 = (float4*)out;
        float4* p4 = (float4*)g_procc;
        for (int idx = t; idx < 128 * 32; idx += 256) {
            int rl = idx >> 5, c4 = idx & 31;
            int node = sRow[rl];
            if (node >= 0) {
                float4 v = ((const float4*)(Cst + rl * 132))[c4];
                o4[(size_t)node * 32 + c4] = v;
                p4[(size_t)(r0 + rl) * 32 + c4] = v;
            }
        }
    }
}

// ---------------------------------------------------------------------------
// Murray head over compacted slots
// ---------------------------------------------------------------------------
__global__ void __launch_bounds__(256) k_murrayc(const float* __restrict__ mw1,
                                                 const float* __restrict__ mb1,
                                                 const float* __restrict__ mw2,
                                                 const float* __restrict__ mb2,
                                                 float* __restrict__ out) {
    __shared__ float w1s[128 * 64];
    __shared__ float b1s[64];
    __shared__ float w2s[64];

    const int t = threadIdx.x;
    for (int i = t; i < 128 * 64; i += 256) w1s[i] = mw1[i];
    if (t < 64) { b1s[t] = mb1[t]; w2s[t] = mw2[t]; }
    __syncthreads();

    const int cnt = g_cnt;
    const float bias2 = mb2[0];
    const int lane = t & 31;
    const int gw = (blockIdx.x * 256 + t) >> 5;
    const int nw = gridDim.x * 8;
    float* mo = out + (size_t)NN * FF;

    for (int slot = gw; slot < cnt; slot += nw) {
        float4 pr = ((const float4*)(g_procc + (size_t)slot * FF))[lane];
        float m0 = b1s[2 * lane], m1 = b1s[2 * lane + 1];
#pragma unroll
        for (int k4 = 0; k4 < 32; k4++) {
            float vx = __shfl_sync(0xffffffffu, pr.x, k4);
            float vy = __shfl_sync(0xffffffffu, pr.y, k4);
            float vz = __shfl_sync(0xffffffffu, pr.z, k4);
            float vw = __shfl_sync(0xffffffffu, pr.w, k4);
            float2 w0  = ((const float2*)&w1s[(k4 * 4 + 0) * 64])[lane];
            float2 w1v = ((const float2*)&w1s[(k4 * 4 + 1) * 64])[lane];
            float2 w2v = ((const float2*)&w1s[(k4 * 4 + 2) * 64])[lane];
            float2 w3v = ((const float2*)&w1s[(k4 * 4 + 3) * 64])[lane];
            m0 = fmaf(vx, w0.x, fmaf(vy, w1v.x, fmaf(vz, w2v.x, fmaf(vw, w3v.x, m0))));
            m1 = fmaf(vx, w0.y, fmaf(vy, w1v.y, fmaf(vz, w2v.y, fmaf(vw, w3v.y, m1))));
        }
        float p = fmaxf(m0, 0.f) * w2s[2 * lane] + fmaxf(m1, 0.f) * w2s[2 * lane + 1];
#pragma unroll
        for (int m = 16; m; m >>= 1) p += __shfl_xor_sync(0xffffffffu, p, m);
        if (lane == 0) mo[g_list[slot]] = 1.f / (1.f + expf(-(p + bias2)));
    }
}

// ---------------------------------------------------------------------------
#define G2_SMEM 69632

extern "C" void kernel_launch(void* const* d_in, const int* in_sizes, int n_in,
                              void* d_out, int out_size) {
    const float* x   = (const float*)d_in[0];
    const int*   ei  = (const int*)d_in[1];
    const int*   ty  = (const int*)d_in[2];
    const float* w1  = (const float*)d_in[3];
    const float* b1  = (const float*)d_in[4];
    const float* w2  = (const float*)d_in[5];
    const float* b2  = (const float*)d_in[6];
    const float* lng = (const float*)d_in[7];
    const float* lnb = (const float*)d_in[8];
    const float* mw1 = (const float*)d_in[9];
    const float* mb1 = (const float*)d_in[10];
    const float* mw2 = (const float*)d_in[11];
    const float* mb2 = (const float*)d_in[12];
    float* out = (float*)d_out;

    static bool attr_done = false;
    if (!attr_done) {
        cudaFuncSetAttribute(k_gemm2c, cudaFuncAttributeMaxDynamicSharedMemorySize, G2_SMEM);
        attr_done = true;
    }

    // FIX: grid must cover NN (200000), not just the 98304 weight elements.
    k_init<<<(NN + 255) / 256, 256>>>(w1, w2);
    k_pass1<<<(EE + 255) / 256, 256>>>(ei);
    k_pass2<<<(EE + 255) / 256, 256>>>(ei);
    k_copy<<<(NN + 7) / 8, 256>>>(x, out);
    k_class<<<(NN + 255) / 256, 256>>>(ty, out);

    dim3 g1(2, (MAXSLOT) / 128);
    k_gemm1c<<<g1, 256>>>(x, b1);
    k_gemm2c<<<MAXSLOT / 128, 256, G2_SMEM>>>(b2, lng, lnb, out);
    k_murrayc<<<592, 256>>>(mw1, mb1, mw2, mb2, out);
}

// round 10
// speedup vs baseline: 2.0272x; 1.4830x over previous
#include <cuda_runtime.h>
#include <math.h>
#include <stdint.h>

#define NN 200000
#define FF 128
#define EE 600000
#define KP 20            // padded smem k-stride (words)
#define MAXSLOT 200064   // 1563 * 128
#define STG_W 2560       // words per stage buffer (128*KP)

// ---------------- scratch ----------------
__device__ int g_min1[NN];
__device__ int g_min2[NN];
__device__ int g_cnt;
__device__ int g_list[MAXSLOT];
__device__ int g_ln0[MAXSLOT];
__device__ int g_ln1[MAXSLOT];
__device__ __align__(16) float g_w1t[256 * 384];              // tf32-rounded, w1t[n][k]
__device__ __align__(16) float g_w2t[128 * 256];              // tf32-rounded, w2t[n][k]
__device__ __align__(16) float g_hc[(size_t)MAXSLOT * 256];   // compact h (tf32 bits)
__device__ __align__(16) float g_procc[(size_t)MAXSLOT * 128];// compact proc

// ---------------- helpers ----------------
__device__ __forceinline__ uint32_t tf32r(float f) {
    uint32_t u;
    asm("cvt.rna.tf32.f32 %0, %1;" : "=r"(u) : "f"(f));
    return u;
}
__device__ __forceinline__ void mma8(float* c, const uint32_t* a, const uint32_t* b) {
    asm volatile(
        "mma.sync.aligned.m16n8k8.row.col.f32.tf32.tf32.f32 "
        "{%0,%1,%2,%3}, {%4,%5,%6,%7}, {%8,%9}, {%0,%1,%2,%3};"
        : "+f"(c[0]), "+f"(c[1]), "+f"(c[2]), "+f"(c[3])
        : "r"(a[0]), "r"(a[1]), "r"(a[2]), "r"(a[3]), "r"(b[0]), "r"(b[1]));
}
__device__ __forceinline__ uint32_t sptr(const void* p) {
    uint32_t a;
    asm("{ .reg .u64 t; cvta.to.shared.u64 t, %1; cvt.u32.u64 %0, t; }" : "=r"(a) : "l"(p));
    return a;
}
__device__ __forceinline__ void cp16(uint32_t dst, const void* src) {
    asm volatile("cp.async.ca.shared.global [%0], [%1], 16;" :: "r"(dst), "l"(src) : "memory");
}
#define CP_COMMIT() asm volatile("cp.async.commit_group;" ::: "memory")
#define CP_WAIT2()  asm volatile("cp.async.wait_group 2;" ::: "memory")

// ---------------- setup: init mins + count + weight prep ----------------
__global__ void k_init(const float* __restrict__ w1, const float* __restrict__ w2) {
    int i = blockIdx.x * blockDim.x + threadIdx.x;
    if (i == 0) g_cnt = 0;
    if (i < NN) { g_min1[i] = NN; g_min2[i] = NN; }
    if (i < 256 * 384) {
        int n = i / 384, k = i % 384;
        g_w1t[i] = __uint_as_float(tf32r(w1[k * 256 + n]));
    }
    if (i < 128 * 256) {
        int n = i / 256, k = i % 256;
        g_w2t[i] = __uint_as_float(tf32r(w2[k * 128 + n]));
    }
}
__global__ void k_pass1(const int* __restrict__ ei) {
    int e = blockIdx.x * blockDim.x + threadIdx.x;
    if (e >= EE) return;
    int s = ei[e], d = ei[EE + e];
    if (s != d) { atomicMin(&g_min1[s], d); atomicMin(&g_min1[d], s); }
}
__global__ void k_pass2(const int* __restrict__ ei) {
    int e = blockIdx.x * blockDim.x + threadIdx.x;
    if (e >= EE) return;
    int s = ei[e], d = ei[EE + e];
    if (s != d) {
        if (d != g_min1[s]) atomicMin(&g_min2[s], d);
        if (s != g_min1[d]) atomicMin(&g_min2[d], s);
    }
}

// ---------------- copy+classify fused: warp per row -----------------------
// out[r] = x[r] unless node will be overwritten by gemm2 scatter (cls==2);
// lane 0 classifies, writes murray default, and compacts.
__global__ void __launch_bounds__(256) k_copyclass(const float* __restrict__ x,
                                                   const int* __restrict__ types,
                                                   float* __restrict__ out) {
    int r = blockIdx.x * 8 + (threadIdx.x >> 5);
    if (r >= NN) return;
    int lane = threadIdx.x & 31;

    int m1 = g_min1[r], m2 = g_min2[r];
    int cls = (types[r] == 1) ? ((m1 < NN && m2 < NN) ? 2 : 1) : 0;
    if (lane == 0) {
        out[(size_t)NN * FF + r] = (cls == 2) ? 0.f : ((cls == 1) ? 0.5f : 0.f);
        // (cls==2 murray overwritten by k_murrayc; value here irrelevant but deterministic)
        if (cls == 2) {
            int slot = atomicAdd(&g_cnt, 1);
            g_list[slot] = r;
            g_ln0[slot] = m1;
            g_ln1[slot] = m2;
        }
    }
    if (cls != 2)   // updated rows fully overwritten later; skip copy
        ((float4*)out)[(size_t)r * 32 + lane] = ((const float4*)x)[(size_t)r * 32 + lane];
}

// ---------------------------------------------------------------------------
// GEMM1 compact, 4-stage cp.async pipeline.
// g_hc[slot] = relu([x[self]|x[n0]|x[n1]] @ w1 + b1)
// grid (2, 1563), early exit on g_cnt. 128x128 tile, K=384 in 24 chunks of 16.
// dyn smem: A stages [4][2560] then B stages [4][2560] (80 KB)
// ---------------------------------------------------------------------------
#define G1_SMEM (8 * STG_W * 4)

__global__ void __launch_bounds__(256, 2) k_gemm1c(const float* __restrict__ x,
                                                   const float* __restrict__ b1) {
    const int r0 = blockIdx.y * 128;
    const int cnt = g_cnt;
    if (r0 >= cnt) return;

    extern __shared__ uint32_t dsm[];
    __shared__ int sSelf[128], sN0[128], sN1[128];

    const int t = threadIdx.x, lane = t & 31, w = t >> 5;
    const int bx = blockIdx.x;

    if (t < 128) {
        int slot = r0 + t;
        bool ok = slot < cnt;
        sSelf[t] = ok ? g_list[slot] : 0;
        sN0[t]   = ok ? g_ln0[slot] : 0;
        sN1[t]   = ok ? g_ln1[slot] : 0;
    }
    __syncthreads();

    const int row = t >> 1, kh = (t & 1) * 8;
    const int mw = w & 3, nw = w >> 2;
    const int gid = lane >> 2, tig = lane & 3;
    const uint32_t sbase = sptr(dsm);
    const uint32_t adst = sbase + (row * KP + kh) * 4;
    const uint32_t bdst = adst + 4 * STG_W * 4;
    const float* bsrc = g_w1t + (size_t)(bx * 128 + row) * 384 + kh;

    float acc[2][8][4];
#pragma unroll
    for (int ms = 0; ms < 2; ms++)
#pragma unroll
        for (int nt = 0; nt < 8; nt++)
#pragma unroll
            for (int j = 0; j < 4; j++) acc[ms][nt][j] = 0.f;

    // stage issue helper (chunk c into stage slot c&3)
    auto issue = [&](int c) {
        const int st = (c & 3) * STG_W * 4;
        const int sel = c >> 3;
        const int src = (sel == 0) ? sSelf[row] : (sel == 1 ? sN0[row] : sN1[row]);
        const float* ap = x + (size_t)src * 128 + (c & 7) * 16 + kh;
        cp16(adst + st, ap);
        cp16(adst + st + 16, ap + 4);
        const float* bp = bsrc + c * 16;
        cp16(bdst + st, bp);
        cp16(bdst + st + 16, bp + 4);
    };

    issue(0); CP_COMMIT();
    issue(1); CP_COMMIT();
    issue(2); CP_COMMIT();

    for (int c = 0; c < 24; c++) {
        CP_WAIT2();
        __syncthreads();
        if (c + 3 < 24) issue(c + 3);
        CP_COMMIT();

        const uint32_t* A = dsm + (c & 3) * STG_W;
        const uint32_t* B = A + 4 * STG_W;
#pragma unroll
        for (int k8 = 0; k8 < 2; k8++) {
            const int kb = k8 * 8;
            uint32_t af[2][4];
#pragma unroll
            for (int ms = 0; ms < 2; ms++) {
                int m = mw * 32 + ms * 16;
                af[ms][0] = A[(m + gid) * KP + kb + tig];
                af[ms][1] = A[(m + 8 + gid) * KP + kb + tig];
                af[ms][2] = A[(m + gid) * KP + kb + tig + 4];
                af[ms][3] = A[(m + 8 + gid) * KP + kb + tig + 4];
            }
#pragma unroll
            for (int nt = 0; nt < 8; nt++) {
                int n = nw * 64 + nt * 8 + gid;
                uint32_t bf[2] = { B[n * KP + kb + tig], B[n * KP + kb + tig + 4] };
                mma8(acc[0][nt], af[0], bf);
                mma8(acc[1][nt], af[1], bf);
            }
        }
    }

    // epilogue: bias + relu -> compact h (tf32 rna so GEMM2 A is pre-rounded)
#pragma unroll
    for (int ms = 0; ms < 2; ms++) {
        int sl = r0 + mw * 32 + ms * 16 + gid;
#pragma unroll
        for (int nt = 0; nt < 8; nt++) {
            int col = bx * 128 + nw * 64 + nt * 8 + tig * 2;
            float bb0 = __ldg(&b1[col]), bb1 = __ldg(&b1[col + 1]);
            if (sl < cnt) {
                uint2 v = { tf32r(fmaxf(acc[ms][nt][0] + bb0, 0.f)),
                            tf32r(fmaxf(acc[ms][nt][1] + bb1, 0.f)) };
                *(uint2*)&g_hc[(size_t)sl * 256 + col] = v;
            }
            if (sl + 8 < cnt) {
                uint2 v = { tf32r(fmaxf(acc[ms][nt][2] + bb0, 0.f)),
                            tf32r(fmaxf(acc[ms][nt][3] + bb1, 0.f)) };
                *(uint2*)&g_hc[(size_t)(sl + 8) * 256 + col] = v;
            }
        }
    }
}

// ---------------------------------------------------------------------------
// GEMM2 compact, 4-stage cp.async pipeline + bias + LN + scatter.
// dyn smem: stages (80 KB) aliased with Cst[128*132] after mainloop
// ---------------------------------------------------------------------------
#define G2_SMEM (8 * STG_W * 4)

__global__ void __launch_bounds__(256, 2) k_gemm2c(const float* __restrict__ b2,
                                                   const float* __restrict__ lng,
                                                   const float* __restrict__ lnb,
                                                   float* __restrict__ out) {
    const int r0 = blockIdx.x * 128;
    const int cnt = g_cnt;
    if (r0 >= cnt) return;

    extern __shared__ uint32_t dsm[];
    float* Cst = (float*)dsm;

    __shared__ int   sRow[128];
    __shared__ float sb2[128], slg[128], slb[128];

    const int t = threadIdx.x, lane = t & 31, w = t >> 5;

    if (t < 128) {
        int slot = r0 + t;
        sRow[t] = (slot < cnt) ? g_list[slot] : -1;
        sb2[t] = b2[t]; slg[t] = lng[t]; slb[t] = lnb[t];
    }
    __syncthreads();

    const int row = t >> 1, kh = (t & 1) * 8;
    const int aslot = min(r0 + row, cnt - 1);
    const int mw = w & 3, nw = w >> 2;
    const int gid = lane >> 2, tig = lane & 3;
    const uint32_t sbase = sptr(dsm);
    const uint32_t adst = sbase + (row * KP + kh) * 4;
    const uint32_t bdst = adst + 4 * STG_W * 4;
    const float* asrc = g_hc + (size_t)aslot * 256 + kh;
    const float* bsrc = g_w2t + (size_t)row * 256 + kh;

    float acc[2][8][4];
#pragma unroll
    for (int ms = 0; ms < 2; ms++)
#pragma unroll
        for (int nt = 0; nt < 8; nt++)
#pragma unroll
            for (int j = 0; j < 4; j++) acc[ms][nt][j] = 0.f;

    auto issue = [&](int c) {
        const int st = (c & 3) * STG_W * 4;
        const float* ap = asrc + c * 16;
        cp16(adst + st, ap);
        cp16(adst + st + 16, ap + 4);
        const float* bp = bsrc + c * 16;
        cp16(bdst + st, bp);
        cp16(bdst + st + 16, bp + 4);
    };

    issue(0); CP_COMMIT();
    issue(1); CP_COMMIT();
    issue(2); CP_COMMIT();

    for (int c = 0; c < 16; c++) {
        CP_WAIT2();
        __syncthreads();
        if (c + 3 < 16) issue(c + 3);
        CP_COMMIT();

        const uint32_t* A = dsm + (c & 3) * STG_W;
        const uint32_t* B = A + 4 * STG_W;
#pragma unroll
        for (int k8 = 0; k8 < 2; k8++) {
            const int kb = k8 * 8;
            uint32_t af[2][4];
#pragma unroll
            for (int ms = 0; ms < 2; ms++) {
                int m = mw * 32 + ms * 16;
                af[ms][0] = A[(m + gid) * KP + kb + tig];
                af[ms][1] = A[(m + 8 + gid) * KP + kb + tig];
                af[ms][2] = A[(m + gid) * KP + kb + tig + 4];
                af[ms][3] = A[(m + 8 + gid) * KP + kb + tig + 4];
            }
#pragma unroll
            for (int nt = 0; nt < 8; nt++) {
                int n = nw * 64 + nt * 8 + gid;
                uint32_t bf[2] = { B[n * KP + kb + tig], B[n * KP + kb + tig + 4] };
                mma8(acc[0][nt], af[0], bf);
                mma8(acc[1][nt], af[1], bf);
            }
        }
    }
    __syncthreads();   // stage buffers dead; Cst aliases them

    // stage bias-added C
#pragma unroll
    for (int ms = 0; ms < 2; ms++) {
        int rl = mw * 32 + ms * 16 + gid;
#pragma unroll
        for (int nt = 0; nt < 8; nt++) {
            int col = nw * 64 + nt * 8 + tig * 2;
            Cst[rl * 132 + col]           = acc[ms][nt][0] + sb2[col];
            Cst[rl * 132 + col + 1]       = acc[ms][nt][1] + sb2[col + 1];
            Cst[(rl + 8) * 132 + col]     = acc[ms][nt][2] + sb2[col];
            Cst[(rl + 8) * 132 + col + 1] = acc[ms][nt][3] + sb2[col + 1];
        }
    }
    __syncthreads();

    // per-row LayerNorm
    if (t < 128) {
        float* rp = Cst + t * 132;
        float s = 0.f, q = 0.f;
#pragma unroll
        for (int j = 0; j < 32; j++) {
            float4 v = ((const float4*)rp)[j];
            s += v.x + v.y + v.z + v.w;
            q += v.x * v.x + v.y * v.y + v.z * v.z + v.w * v.w;
        }
        float mean = s * (1.f / 128.f);
        float var  = q * (1.f / 128.f) - mean * mean;
        float rs   = rsqrtf(var + 1e-5f);
#pragma unroll
        for (int j = 0; j < 32; j++) {
            float4 v = ((const float4*)rp)[j];
            v.x = (v.x - mean) * rs * slg[4 * j]     + slb[4 * j];
            v.y = (v.y - mean) * rs * slg[4 * j + 1] + slb[4 * j + 1];
            v.z = (v.z - mean) * rs * slg[4 * j + 2] + slb[4 * j + 2];
            v.w = (v.w - mean) * rs * slg[4 * j + 3] + slb[4 * j + 3];
            ((float4*)rp)[j] = v;
        }
    }
    __syncthreads();

    // scatter: out[node] = proc ; g_procc[slot] = proc
    {
        float4* o4 = (float4*)out;
        float4* p4 = (float4*)g_procc;
        for (int idx = t; idx < 128 * 32; idx += 256) {
            int rl = idx >> 5, c4 = idx & 31;
            int node = sRow[rl];
            if (node >= 0) {
                float4 v = ((const float4*)(Cst + rl * 132))[c4];
                o4[(size_t)node * 32 + c4] = v;
                p4[(size_t)(r0 + rl) * 32 + c4] = v;
            }
        }
    }
}

// ---------------------------------------------------------------------------
// Murray head over compacted slots
// ---------------------------------------------------------------------------
__global__ void __launch_bounds__(256) k_murrayc(const float* __restrict__ mw1,
                                                 const float* __restrict__ mb1,
                                                 const float* __restrict__ mw2,
                                                 const float* __restrict__ mb2,
                                                 float* __restrict__ out) {
    __shared__ float w1s[128 * 64];
    __shared__ float b1s[64];
    __shared__ float w2s[64];

    const int t = threadIdx.x;
    for (int i = t; i < 128 * 64; i += 256) w1s[i] = mw1[i];
    if (t < 64) { b1s[t] = mb1[t]; w2s[t] = mw2[t]; }
    __syncthreads();

    const int cnt = g_cnt;
    const float bias2 = mb2[0];
    const int lane = t & 31;
    const int gw = (blockIdx.x * 256 + t) >> 5;
    const int nw = gridDim.x * 8;
    float* mo = out + (size_t)NN * FF;

    for (int slot = gw; slot < cnt; slot += nw) {
        float4 pr = ((const float4*)(g_procc + (size_t)slot * FF))[lane];
        float m0 = b1s[2 * lane], m1 = b1s[2 * lane + 1];
#pragma unroll
        for (int k4 = 0; k4 < 32; k4++) {
            float vx = __shfl_sync(0xffffffffu, pr.x, k4);
            float vy = __shfl_sync(0xffffffffu, pr.y, k4);
            float vz = __shfl_sync(0xffffffffu, pr.z, k4);
            float vw = __shfl_sync(0xffffffffu, pr.w, k4);
            float2 w0  = ((const float2*)&w1s[(k4 * 4 + 0) * 64])[lane];
            float2 w1v = ((const float2*)&w1s[(k4 * 4 + 1) * 64])[lane];
            float2 w2v = ((const float2*)&w1s[(k4 * 4 + 2) * 64])[lane];
            float2 w3v = ((const float2*)&w1s[(k4 * 4 + 3) * 64])[lane];
            m0 = fmaf(vx, w0.x, fmaf(vy, w1v.x, fmaf(vz, w2v.x, fmaf(vw, w3v.x, m0))));
            m1 = fmaf(vx, w0.y, fmaf(vy, w1v.y, fmaf(vz, w2v.y, fmaf(vw, w3v.y, m1))));
        }
        float p = fmaxf(m0, 0.f) * w2s[2 * lane] + fmaxf(m1, 0.f) * w2s[2 * lane + 1];
#pragma unroll
        for (int m = 16; m; m >>= 1) p += __shfl_xor_sync(0xffffffffu, p, m);
        if (lane == 0) mo[g_list[slot]] = 1.f / (1.f + expf(-(p + bias2)));
    }
}

// ---------------------------------------------------------------------------
extern "C" void kernel_launch(void* const* d_in, const int* in_sizes, int n_in,
                              void* d_out, int out_size) {
    const float* x   = (const float*)d_in[0];
    const int*   ei  = (const int*)d_in[1];
    const int*   ty  = (const int*)d_in[2];
    const float* w1  = (const float*)d_in[3];
    const float* b1  = (const float*)d_in[4];
    const float* w2  = (const float*)d_in[5];
    const float* b2  = (const float*)d_in[6];
    const float* lng = (const float*)d_in[7];
    const float* lnb = (const float*)d_in[8];
    const float* mw1 = (const float*)d_in[9];
    const float* mb1 = (const float*)d_in[10];
    const float* mw2 = (const float*)d_in[11];
    const float* mb2 = (const float*)d_in[12];
    float* out = (float*)d_out;

    static bool attr_done = false;
    if (!attr_done) {
        cudaFuncSetAttribute(k_gemm1c, cudaFuncAttributeMaxDynamicSharedMemorySize, G1_SMEM);
        cudaFuncSetAttribute(k_gemm2c, cudaFuncAttributeMaxDynamicSharedMemorySize, G2_SMEM);
        attr_done = true;
    }

    k_init<<<(NN + 255) / 256, 256>>>(w1, w2);
    k_pass1<<<(EE + 255) / 256, 256>>>(ei);
    k_pass2<<<(EE + 255) / 256, 256>>>(ei);
    k_copyclass<<<(NN + 7) / 8, 256>>>(x, ty, out);

    dim3 g1(2, MAXSLOT / 128);
    k_gemm1c<<<g1, 256, G1_SMEM>>>(x, b1);
    k_gemm2c<<<MAXSLOT / 128, 256, G2_SMEM>>>(b2, lng, lnb, out);
    k_murrayc<<<592, 256>>>(mw1, mb1, mw2, mb2, out);
}

// round 11
// speedup vs baseline: 2.0468x; 1.0096x over previous
#include <cuda_runtime.h>
#include <math.h>
#include <stdint.h>

#define NN 200000
#define FF 128
#define EE 600000
#define KP 20            // padded smem k-stride (words)
#define MAXSLOT 200064   // 1563 * 128
#define STG_W 2560       // words per stage buffer (128*KP)

// ---------------- scratch ----------------
__device__ int g_min1[NN];
__device__ int g_min2[NN];
__device__ int g_cnt;
__device__ int g_list[MAXSLOT];
__device__ int g_ln0[MAXSLOT];
__device__ int g_ln1[MAXSLOT];
__device__ __align__(16) float g_w1t[256 * 384];              // tf32-rounded, w1t[n][k]
__device__ __align__(16) float g_w2t[128 * 256];              // tf32-rounded, w2t[n][k]
__device__ __align__(16) float g_hc[(size_t)MAXSLOT * 256];   // compact h (tf32 bits)

// ---------------- helpers ----------------
__device__ __forceinline__ uint32_t tf32r(float f) {
    uint32_t u;
    asm("cvt.rna.tf32.f32 %0, %1;" : "=r"(u) : "f"(f));
    return u;
}
__device__ __forceinline__ void mma8(float* c, const uint32_t* a, const uint32_t* b) {
    asm volatile(
        "mma.sync.aligned.m16n8k8.row.col.f32.tf32.tf32.f32 "
        "{%0,%1,%2,%3}, {%4,%5,%6,%7}, {%8,%9}, {%0,%1,%2,%3};"
        : "+f"(c[0]), "+f"(c[1]), "+f"(c[2]), "+f"(c[3])
        : "r"(a[0]), "r"(a[1]), "r"(a[2]), "r"(a[3]), "r"(b[0]), "r"(b[1]));
}
__device__ __forceinline__ uint32_t sptr(const void* p) {
    uint32_t a;
    asm("{ .reg .u64 t; cvta.to.shared.u64 t, %1; cvt.u32.u64 %0, t; }" : "=r"(a) : "l"(p));
    return a;
}
__device__ __forceinline__ void cp16(uint32_t dst, const void* src) {
    asm volatile("cp.async.ca.shared.global [%0], [%1], 16;" :: "r"(dst), "l"(src) : "memory");
}
#define CP_COMMIT() asm volatile("cp.async.commit_group;" ::: "memory")
#define CP_WAIT2()  asm volatile("cp.async.wait_group 2;" ::: "memory")

// ---------------- setup: init mins + count + weight prep ----------------
__global__ void k_init(const float* __restrict__ w1, const float* __restrict__ w2) {
    int i = blockIdx.x * blockDim.x + threadIdx.x;
    if (i == 0) g_cnt = 0;
    if (i < NN) { g_min1[i] = NN; g_min2[i] = NN; }
    if (i < 256 * 384) {
        int n = i / 384, k = i % 384;
        g_w1t[i] = __uint_as_float(tf32r(w1[k * 256 + n]));
    }
    if (i < 128 * 256) {
        int n = i / 256, k = i % 256;
        g_w2t[i] = __uint_as_float(tf32r(w2[k * 128 + n]));
    }
}
__global__ void k_pass1(const int* __restrict__ ei) {
    int e = blockIdx.x * blockDim.x + threadIdx.x;
    if (e >= EE) return;
    int s = ei[e], d = ei[EE + e];
    if (s != d) { atomicMin(&g_min1[s], d); atomicMin(&g_min1[d], s); }
}
__global__ void k_pass2(const int* __restrict__ ei) {
    int e = blockIdx.x * blockDim.x + threadIdx.x;
    if (e >= EE) return;
    int s = ei[e], d = ei[EE + e];
    if (s != d) {
        if (d != g_min1[s]) atomicMin(&g_min2[s], d);
        if (s != g_min1[d]) atomicMin(&g_min2[d], s);
    }
}

// ---------------- pure copy: out = x (straightline, full HBM rate) -------
__global__ void __launch_bounds__(256) k_copy(const float* __restrict__ x,
                                              float* __restrict__ out) {
    int row = blockIdx.x * 8 + (threadIdx.x >> 5);
    if (row >= NN) return;
    int c = threadIdx.x & 31;
    ((float4*)out)[(size_t)row * 32 + c] = ((const float4*)x)[(size_t)row * 32 + c];
}

// ---------------- classify + compact + murray defaults -------------------
__global__ void k_class(const int* __restrict__ types, float* __restrict__ out) {
    int r = blockIdx.x * blockDim.x + threadIdx.x;
    if (r >= NN) return;
    int m1 = g_min1[r], m2 = g_min2[r];
    int cls = (types[r] == 1) ? ((m1 < NN && m2 < NN) ? 2 : 1) : 0;
    out[(size_t)NN * FF + r] = (cls == 1) ? 0.5f : 0.f;  // cls==2 overwritten by gemm2
    if (cls == 2) {
        int slot = atomicAdd(&g_cnt, 1);
        g_list[slot] = r;
        g_ln0[slot] = m1;
        g_ln1[slot] = m2;
    }
}

// ---------------------------------------------------------------------------
// GEMM1 compact, 4-stage cp.async pipeline.
// g_hc[slot] = relu([x[self]|x[n0]|x[n1]] @ w1 + b1)
// grid (2, 1563), early exit on g_cnt. 128x128 tile, K=384 in 24 chunks of 16.
// ---------------------------------------------------------------------------
#define G1_SMEM (8 * STG_W * 4)

__global__ void __launch_bounds__(256, 2) k_gemm1c(const float* __restrict__ x,
                                                   const float* __restrict__ b1) {
    const int r0 = blockIdx.y * 128;
    const int cnt = g_cnt;
    if (r0 >= cnt) return;

    extern __shared__ uint32_t dsm[];
    __shared__ int sSelf[128], sN0[128], sN1[128];

    const int t = threadIdx.x, lane = t & 31, w = t >> 5;
    const int bx = blockIdx.x;

    if (t < 128) {
        int slot = r0 + t;
        bool ok = slot < cnt;
        sSelf[t] = ok ? g_list[slot] : 0;
        sN0[t]   = ok ? g_ln0[slot] : 0;
        sN1[t]   = ok ? g_ln1[slot] : 0;
    }
    __syncthreads();

    const int row = t >> 1, kh = (t & 1) * 8;
    const int mw = w & 3, nw = w >> 2;
    const int gid = lane >> 2, tig = lane & 3;
    const uint32_t sbase = sptr(dsm);
    const uint32_t adst = sbase + (row * KP + kh) * 4;
    const uint32_t bdst = adst + 4 * STG_W * 4;
    const float* bsrc = g_w1t + (size_t)(bx * 128 + row) * 384 + kh;

    float acc[2][8][4];
#pragma unroll
    for (int ms = 0; ms < 2; ms++)
#pragma unroll
        for (int nt = 0; nt < 8; nt++)
#pragma unroll
            for (int j = 0; j < 4; j++) acc[ms][nt][j] = 0.f;

    auto issue = [&](int c) {
        const int st = (c & 3) * STG_W * 4;
        const int sel = c >> 3;
        const int src = (sel == 0) ? sSelf[row] : (sel == 1 ? sN0[row] : sN1[row]);
        const float* ap = x + (size_t)src * 128 + (c & 7) * 16 + kh;
        cp16(adst + st, ap);
        cp16(adst + st + 16, ap + 4);
        const float* bp = bsrc + c * 16;
        cp16(bdst + st, bp);
        cp16(bdst + st + 16, bp + 4);
    };

    issue(0); CP_COMMIT();
    issue(1); CP_COMMIT();
    issue(2); CP_COMMIT();

    for (int c = 0; c < 24; c++) {
        CP_WAIT2();
        __syncthreads();
        if (c + 3 < 24) issue(c + 3);
        CP_COMMIT();

        const uint32_t* A = dsm + (c & 3) * STG_W;
        const uint32_t* B = A + 4 * STG_W;
#pragma unroll
        for (int k8 = 0; k8 < 2; k8++) {
            const int kb = k8 * 8;
            uint32_t af[2][4];
#pragma unroll
            for (int ms = 0; ms < 2; ms++) {
                int m = mw * 32 + ms * 16;
                af[ms][0] = A[(m + gid) * KP + kb + tig];
                af[ms][1] = A[(m + 8 + gid) * KP + kb + tig];
                af[ms][2] = A[(m + gid) * KP + kb + tig + 4];
                af[ms][3] = A[(m + 8 + gid) * KP + kb + tig + 4];
            }
#pragma unroll
            for (int nt = 0; nt < 8; nt++) {
                int n = nw * 64 + nt * 8 + gid;
                uint32_t bf[2] = { B[n * KP + kb + tig], B[n * KP + kb + tig + 4] };
                mma8(acc[0][nt], af[0], bf);
                mma8(acc[1][nt], af[1], bf);
            }
        }
    }

    // epilogue: bias + relu -> compact h (tf32 rna so GEMM2 A is pre-rounded)
#pragma unroll
    for (int ms = 0; ms < 2; ms++) {
        int sl = r0 + mw * 32 + ms * 16 + gid;
#pragma unroll
        for (int nt = 0; nt < 8; nt++) {
            int col = bx * 128 + nw * 64 + nt * 8 + tig * 2;
            float bb0 = __ldg(&b1[col]), bb1 = __ldg(&b1[col + 1]);
            if (sl < cnt) {
                uint2 v = { tf32r(fmaxf(acc[0][nt][2 * ms]     + bb0, 0.f)),
                            tf32r(fmaxf(acc[0][nt][2 * ms + 1] + bb1, 0.f)) };
                // NOTE: acc index mapping below is the original (correct) one;
                // see the unfused lines that follow.
                (void)v;
            }
        }
    }
    // (original, correct epilogue)
#pragma unroll
    for (int ms = 0; ms < 2; ms++) {
        int sl = r0 + mw * 32 + ms * 16 + gid;
#pragma unroll
        for (int nt = 0; nt < 8; nt++) {
            int col = bx * 128 + nw * 64 + nt * 8 + tig * 2;
            float bb0 = __ldg(&b1[col]), bb1 = __ldg(&b1[col + 1]);
            if (sl < cnt) {
                uint2 v = { tf32r(fmaxf(acc[ms][nt][0] + bb0, 0.f)),
                            tf32r(fmaxf(acc[ms][nt][1] + bb1, 0.f)) };
                *(uint2*)&g_hc[(size_t)sl * 256 + col] = v;
            }
            if (sl + 8 < cnt) {
                uint2 v = { tf32r(fmaxf(acc[ms][nt][2] + bb0, 0.f)),
                            tf32r(fmaxf(acc[ms][nt][3] + bb1, 0.f)) };
                *(uint2*)&g_hc[(size_t)(sl + 8) * 256 + col] = v;
            }
        }
    }
}

// ---------------------------------------------------------------------------
// GEMM2 compact, 4-stage cp.async pipeline + bias + LN + scatter + MURRAY.
// dyn smem: stages (80 KB) aliased with Cst[128*132] after mainloop.
// ---------------------------------------------------------------------------
#define G2_SMEM (8 * STG_W * 4)

__global__ void __launch_bounds__(256, 2) k_gemm2c(const float* __restrict__ b2,
                                                   const float* __restrict__ lng,
                                                   const float* __restrict__ lnb,
                                                   const float* __restrict__ mw1,
                                                   const float* __restrict__ mb1,
                                                   const float* __restrict__ mw2,
                                                   const float* __restrict__ mb2,
                                                   float* __restrict__ out) {
    const int r0 = blockIdx.x * 128;
    const int cnt = g_cnt;
    if (r0 >= cnt) return;

    extern __shared__ uint32_t dsm[];
    float* Cst = (float*)dsm;

    __shared__ int   sRow[128];
    __shared__ float sb2[128], slg[128], slb[128];

    const int t = threadIdx.x, lane = t & 31, w = t >> 5;

    if (t < 128) {
        int slot = r0 + t;
        sRow[t] = (slot < cnt) ? g_list[slot] : -1;
        sb2[t] = b2[t]; slg[t] = lng[t]; slb[t] = lnb[t];
    }
    __syncthreads();

    const int row = t >> 1, kh = (t & 1) * 8;
    const int aslot = min(r0 + row, cnt - 1);
    const int mw = w & 3, nw = w >> 2;
    const int gid = lane >> 2, tig = lane & 3;
    const uint32_t sbase = sptr(dsm);
    const uint32_t adst = sbase + (row * KP + kh) * 4;
    const uint32_t bdst = adst + 4 * STG_W * 4;
    const float* asrc = g_hc + (size_t)aslot * 256 + kh;
    const float* bsrc = g_w2t + (size_t)row * 256 + kh;

    float acc[2][8][4];
#pragma unroll
    for (int ms = 0; ms < 2; ms++)
#pragma unroll
        for (int nt = 0; nt < 8; nt++)
#pragma unroll
            for (int j = 0; j < 4; j++) acc[ms][nt][j] = 0.f;

    auto issue = [&](int c) {
        const int st = (c & 3) * STG_W * 4;
        const float* ap = asrc + c * 16;
        cp16(adst + st, ap);
        cp16(adst + st + 16, ap + 4);
        const float* bp = bsrc + c * 16;
        cp16(bdst + st, bp);
        cp16(bdst + st + 16, bp + 4);
    };

    issue(0); CP_COMMIT();
    issue(1); CP_COMMIT();
    issue(2); CP_COMMIT();

    for (int c = 0; c < 16; c++) {
        CP_WAIT2();
        __syncthreads();
        if (c + 3 < 16) issue(c + 3);
        CP_COMMIT();

        const uint32_t* A = dsm + (c & 3) * STG_W;
        const uint32_t* B = A + 4 * STG_W;
#pragma unroll
        for (int k8 = 0; k8 < 2; k8++) {
            const int kb = k8 * 8;
            uint32_t af[2][4];
#pragma unroll
            for (int ms = 0; ms < 2; ms++) {
                int m = mw * 32 + ms * 16;
                af[ms][0] = A[(m + gid) * KP + kb + tig];
                af[ms][1] = A[(m + 8 + gid) * KP + kb + tig];
                af[ms][2] = A[(m + gid) * KP + kb + tig + 4];
                af[ms][3] = A[(m + 8 + gid) * KP + kb + tig + 4];
            }
#pragma unroll
            for (int nt = 0; nt < 8; nt++) {
                int n = nw * 64 + nt * 8 + gid;
                uint32_t bf[2] = { B[n * KP + kb + tig], B[n * KP + kb + tig + 4] };
                mma8(acc[0][nt], af[0], bf);
                mma8(acc[1][nt], af[1], bf);
            }
        }
    }
    __syncthreads();   // stage buffers dead; Cst aliases them

    // stage bias-added C
#pragma unroll
    for (int ms = 0; ms < 2; ms++) {
        int rl = mw * 32 + ms * 16 + gid;
#pragma unroll
        for (int nt = 0; nt < 8; nt++) {
            int col = nw * 64 + nt * 8 + tig * 2;
            Cst[rl * 132 + col]           = acc[ms][nt][0] + sb2[col];
            Cst[rl * 132 + col + 1]       = acc[ms][nt][1] + sb2[col + 1];
            Cst[(rl + 8) * 132 + col]     = acc[ms][nt][2] + sb2[col];
            Cst[(rl + 8) * 132 + col + 1] = acc[ms][nt][3] + sb2[col + 1];
        }
    }
    __syncthreads();

    // per-row LayerNorm
    if (t < 128) {
        float* rp = Cst + t * 132;
        float s = 0.f, q = 0.f;
#pragma unroll
        for (int j = 0; j < 32; j++) {
            float4 v = ((const float4*)rp)[j];
            s += v.x + v.y + v.z + v.w;
            q += v.x * v.x + v.y * v.y + v.z * v.z + v.w * v.w;
        }
        float mean = s * (1.f / 128.f);
        float var  = q * (1.f / 128.f) - mean * mean;
        float rs   = rsqrtf(var + 1e-5f);
#pragma unroll
        for (int j = 0; j < 32; j++) {
            float4 v = ((const float4*)rp)[j];
            v.x = (v.x - mean) * rs * slg[4 * j]     + slb[4 * j];
            v.y = (v.y - mean) * rs * slg[4 * j + 1] + slb[4 * j + 1];
            v.z = (v.z - mean) * rs * slg[4 * j + 2] + slb[4 * j + 2];
            v.w = (v.w - mean) * rs * slg[4 * j + 3] + slb[4 * j + 3];
            ((float4*)rp)[j] = v;
        }
    }
    __syncthreads();

    // scatter: out[node] = proc
    {
        float4* o4 = (float4*)out;
        for (int idx = t; idx < 128 * 32; idx += 256) {
            int rl = idx >> 5, c4 = idx & 31;
            int node = sRow[rl];
            if (node >= 0)
                o4[(size_t)node * 32 + c4] = ((const float4*)(Cst + rl * 132))[c4];
        }
    }

    // fused murray head: warp per row, proc from Cst, weights via L1 (__ldg)
    {
        const float bias2 = __ldg(mb2);
        const float mb1a = __ldg(&mb1[2 * lane]);
        const float mb1b = __ldg(&mb1[2 * lane + 1]);
        const float w2a  = __ldg(&mw2[2 * lane]);
        const float w2b  = __ldg(&mw2[2 * lane + 1]);
        float* mo = out + (size_t)NN * FF;
        for (int rl = w; rl < 128; rl += 8) {
            int node = sRow[rl];
            if (node < 0) continue;
            float4 pr = ((const float4*)(Cst + rl * 132))[lane];
            float m0 = mb1a, m1 = mb1b;
#pragma unroll
            for (int k4 = 0; k4 < 32; k4++) {
                float vx = __shfl_sync(0xffffffffu, pr.x, k4);
                float vy = __shfl_sync(0xffffffffu, pr.y, k4);
                float vz = __shfl_sync(0xffffffffu, pr.z, k4);
                float vw = __shfl_sync(0xffffffffu, pr.w, k4);
                float2 w0  = __ldg((const float2*)&mw1[(k4 * 4 + 0) * 64 + 2 * lane]);
                float2 w1v = __ldg((const float2*)&mw1[(k4 * 4 + 1) * 64 + 2 * lane]);
                float2 w2v = __ldg((const float2*)&mw1[(k4 * 4 + 2) * 64 + 2 * lane]);
                float2 w3v = __ldg((const float2*)&mw1[(k4 * 4 + 3) * 64 + 2 * lane]);
                m0 = fmaf(vx, w0.x, fmaf(vy, w1v.x, fmaf(vz, w2v.x, fmaf(vw, w3v.x, m0))));
                m1 = fmaf(vx, w0.y, fmaf(vy, w1v.y, fmaf(vz, w2v.y, fmaf(vw, w3v.y, m1))));
            }
            float p = fmaxf(m0, 0.f) * w2a + fmaxf(m1, 0.f) * w2b;
#pragma unroll
            for (int m = 16; m; m >>= 1) p += __shfl_xor_sync(0xffffffffu, p, m);
            if (lane == 0) mo[node] = 1.f / (1.f + expf(-(p + bias2)));
        }
    }
}

// ---------------------------------------------------------------------------
extern "C" void kernel_launch(void* const* d_in, const int* in_sizes, int n_in,
                              void* d_out, int out_size) {
    const float* x   = (const float*)d_in[0];
    const int*   ei  = (const int*)d_in[1];
    const int*   ty  = (const int*)d_in[2];
    const float* w1  = (const float*)d_in[3];
    const float* b1  = (const float*)d_in[4];
    const float* w2  = (const float*)d_in[5];
    const float* b2  = (const float*)d_in[6];
    const float* lng = (const float*)d_in[7];
    const float* lnb = (const float*)d_in[8];
    const float* mw1 = (const float*)d_in[9];
    const float* mb1 = (const float*)d_in[10];
    const float* mw2 = (const float*)d_in[11];
    const float* mb2 = (const float*)d_in[12];
    float* out = (float*)d_out;

    static bool attr_done = false;
    if (!attr_done) {
        cudaFuncSetAttribute(k_gemm1c, cudaFuncAttributeMaxDynamicSharedMemorySize, G1_SMEM);
        cudaFuncSetAttribute(k_gemm2c, cudaFuncAttributeMaxDynamicSharedMemorySize, G2_SMEM);
        attr_done = true;
    }

    k_init<<<(NN + 255) / 256, 256>>>(w1, w2);
    k_pass1<<<(EE + 255) / 256, 256>>>(ei);
    k_pass2<<<(EE + 255) / 256, 256>>>(ei);
    k_copy<<<(NN + 7) / 8, 256>>>(x, out);
    k_class<<<(NN + 255) / 256, 256>>>(ty, out);

    dim3 g1(2, MAXSLOT / 128);
    k_gemm1c<<<g1, 256, G1_SMEM>>>(x, b1);
    k_gemm2c<<<MAXSLOT / 128, 256, G2_SMEM>>>(b2, lng, lnb, mw1, mb1, mw2, mb2, out);
}